// round 9
// baseline (speedup 1.0000x reference)
#include <cuda_runtime.h>
#include <cstdint>

// Problem dims (fixed)
#define B_  16
#define U_  64
#define T_  128
#define E_  128
#define HID_ 256
#define H_  4
#define ENC_H_ 128
#define IN_DIM_ 32

typedef unsigned long long ull;

// Scratch (device globals: no allocation allowed)
__device__ float g_qu[B_ * U_ * HID_];    // ue @ fw1[:E]          (1024 x 256)
__device__ float g_kh[B_ * T_ * HID_];    // te @ fw1[E:]          (2048 x 256)
__device__ float g_qb[H_ * HID_];         // head_q @ fw1[:E] + fb1 (4 x 256)
__device__ float g_part[4][B_ * H_ * U_ * T_];  // d-quadrant partial sums

// ---- packed f32x2 helpers (Blackwell) ----
__device__ __forceinline__ ull add2(ull a, ull b) {
    ull r;
    asm("add.rn.f32x2 %0, %1, %2;" : "=l"(r) : "l"(a), "l"(b));
    return r;
}
__device__ __forceinline__ void fma2(ull& acc, ull a, ull b) {
    asm("fma.rn.f32x2 %0, %1, %2, %0;" : "+l"(acc) : "l"(a), "l"(b));
}
__device__ __forceinline__ ull relu2(ull x) {
    float lo, hi;
    asm("mov.b64 {%0,%1}, %2;" : "=f"(lo), "=f"(hi) : "l"(x));
    lo = fmaxf(lo, 0.f);
    hi = fmaxf(hi, 0.f);
    ull r;
    asm("mov.b64 %0, {%1,%2};" : "=l"(r) : "f"(lo), "f"(hi));
    return r;
}
__device__ __forceinline__ float hsum2(ull x) {
    float lo, hi;
    asm("mov.b64 {%0,%1}, %2;" : "=f"(lo), "=f"(hi) : "l"(x));
    return lo + hi;
}

// ---------------------------------------------------------------------------
// Fused encoder: blocks [0,128) = UAV (8 rows each), [128,384) = task,
// block 384 = qb.  512 threads: j = tid&127 owns output col j,
// rg = tid>>7 (0..3) owns rows 2rg, 2rg+1.
// Weight loads: scalar LDG.32, consecutive j across warp -> 1 wavefront.
// Activation loads: float4 LDS, warp-uniform -> broadcast.
// __launch_bounds__(512, 2) caps regs at 64 so 2 blocks (32 warps) co-reside.
// ---------------------------------------------------------------------------
#define ENC_ROWS 8

__global__ __launch_bounds__(512, 2) void enc_fused_kernel(
    const float* __restrict__ uav_feat, const float* __restrict__ task_feat,
    const float* __restrict__ uw0, const float* __restrict__ ub0,
    const float* __restrict__ uw1, const float* __restrict__ ub1,
    const float* __restrict__ uw2, const float* __restrict__ ub2,
    const float* __restrict__ tw0, const float* __restrict__ tb0,
    const float* __restrict__ tw1, const float* __restrict__ tb1,
    const float* __restrict__ tw2, const float* __restrict__ tb2,
    const float* __restrict__ head_q, const float* __restrict__ fw1,
    const float* __restrict__ fb1)
{
    const int bx = blockIdx.x;
    const int tid = threadIdx.x;

    // ---------------- qb block ----------------
    if (bx == 384) {
        int d  = tid & 255;
        int h0 = tid >> 8;            // 0..1
        #pragma unroll
        for (int h = h0; h < H_; h += 2) {
            float acc = fb1[d];
            #pragma unroll 8
            for (int k = 0; k < E_; ++k)
                acc += head_q[h * E_ + k] * fw1[k * HID_ + d];
            g_qb[h * HID_ + d] = acc;
        }
        return;
    }

    const int is_task = (bx >= 128);
    const float* x  = is_task ? task_feat : uav_feat;
    const float* w0 = is_task ? tw0 : uw0;
    const float* b0 = is_task ? tb0 : ub0;
    const float* w1 = is_task ? tw1 : uw1;
    const float* b1 = is_task ? tb1 : ub1;
    const float* w2 = is_task ? tw2 : uw2;
    const float* b2 = is_task ? tb2 : ub2;
    float* out      = is_task ? g_kh : g_qu;
    const int fw1_off = is_task ? E_ : 0;
    const int row0 = (is_task ? (bx - 128) : bx) * ENC_ROWS;

    __shared__ float xs[ENC_ROWS][IN_DIM_];
    __shared__ float bufA[ENC_ROWS][ENC_H_];
    __shared__ float bufB[ENC_ROWS][ENC_H_];

    // load 8x32 input tile
    if (tid < ENC_ROWS * IN_DIM_)
        xs[tid >> 5][tid & 31] = x[(row0 + (tid >> 5)) * IN_DIM_ + (tid & 31)];
    __syncthreads();

    const int j  = tid & 127;
    const int r0 = (tid >> 7) * 2;    // rows r0, r0+1 (warp-uniform)
    float acc[2];

    // ---- layer 0: 32 -> 128, relu ----
    acc[0] = acc[1] = b0[j];
    #pragma unroll
    for (int k = 0; k < IN_DIM_; k += 4) {
        float wv0 = w0[(k + 0) * ENC_H_ + j];
        float wv1 = w0[(k + 1) * ENC_H_ + j];
        float wv2 = w0[(k + 2) * ENC_H_ + j];
        float wv3 = w0[(k + 3) * ENC_H_ + j];
        #pragma unroll
        for (int r = 0; r < 2; ++r) {
            float4 xa = *(const float4*)&xs[r0 + r][k];
            acc[r] += xa.x * wv0 + xa.y * wv1 + xa.z * wv2 + xa.w * wv3;
        }
    }
    #pragma unroll
    for (int r = 0; r < 2; ++r) bufA[r0 + r][j] = fmaxf(acc[r], 0.f);
    __syncthreads();

    // ---- layer 1: 128 -> 128, relu ----
    acc[0] = acc[1] = b1[j];
    #pragma unroll 8
    for (int k = 0; k < ENC_H_; k += 4) {
        float wv0 = w1[(k + 0) * ENC_H_ + j];
        float wv1 = w1[(k + 1) * ENC_H_ + j];
        float wv2 = w1[(k + 2) * ENC_H_ + j];
        float wv3 = w1[(k + 3) * ENC_H_ + j];
        #pragma unroll
        for (int r = 0; r < 2; ++r) {
            float4 xa = *(const float4*)&bufA[r0 + r][k];
            acc[r] += xa.x * wv0 + xa.y * wv1 + xa.z * wv2 + xa.w * wv3;
        }
    }
    #pragma unroll
    for (int r = 0; r < 2; ++r) bufB[r0 + r][j] = fmaxf(acc[r], 0.f);
    __syncthreads();

    // ---- layer 2: 128 -> 128 (no relu) ----
    acc[0] = acc[1] = b2[j];
    #pragma unroll 8
    for (int k = 0; k < ENC_H_; k += 4) {
        float wv0 = w2[(k + 0) * ENC_H_ + j];
        float wv1 = w2[(k + 1) * ENC_H_ + j];
        float wv2 = w2[(k + 2) * ENC_H_ + j];
        float wv3 = w2[(k + 3) * ENC_H_ + j];
        #pragma unroll
        for (int r = 0; r < 2; ++r) {
            float4 xa = *(const float4*)&bufB[r0 + r][k];
            acc[r] += xa.x * wv0 + xa.y * wv1 + xa.z * wv2 + xa.w * wv3;
        }
    }
    __syncthreads();   // bufA reads done
    #pragma unroll
    for (int r = 0; r < 2; ++r) bufA[r0 + r][j] = acc[r];
    __syncthreads();

    // ---- projection through fw1 slice: 128 -> 256 ----
    const float* wp = fw1 + fw1_off * HID_;
    #pragma unroll
    for (int p = 0; p < 2; ++p) {
        int col = j + p * 128;
        acc[0] = acc[1] = 0.f;
        #pragma unroll 8
        for (int k = 0; k < E_; k += 4) {
            float wv0 = wp[(k + 0) * HID_ + col];
            float wv1 = wp[(k + 1) * HID_ + col];
            float wv2 = wp[(k + 2) * HID_ + col];
            float wv3 = wp[(k + 3) * HID_ + col];
            #pragma unroll
            for (int r = 0; r < 2; ++r) {
                float4 xa = *(const float4*)&bufA[r0 + r][k];
                acc[r] += xa.x * wv0 + xa.y * wv1 + xa.z * wv2 + xa.w * wv3;
            }
        }
        #pragma unroll
        for (int r = 0; r < 2; ++r)
            out[(size_t)(row0 + r0 + r) * HID_ + col] = acc[r];
    }
}

// ---------------------------------------------------------------------------
// Stage E (d-split): partial[dq][z][u][t] =
//   sum_{d in quad} relu(qu[b,u,d]+qb[h,d]+kh[b,t,d]) * fw2[d]
// Block: (dq, z). Tile 64u x 128t x 64d, 512 threads, thread tile 4u x 4t.
// tg = tid&31 -> t = tg + 32*jj;  ug = tid>>5 -> u = 4*ug + i (warp-uniform).
// q/w loads broadcast; k loads conflict-free (stride 68).
// ---------------------------------------------------------------------------
#define DQ 64
#define QSTRIDE 68
#define SMEM_E_FLOATS (64 * QSTRIDE + 128 * QSTRIDE + DQ)
#define SMEM_E_BYTES  (SMEM_E_FLOATS * 4)

__global__ __launch_bounds__(512, 2) void stageE_k(
    const float* __restrict__ fw2)
{
    extern __shared__ float smem[];
    float* qs   = smem;                        // [64][68]
    float* ks   = smem + 64 * QSTRIDE;         // [128][68]
    float* fw2s = ks + 128 * QSTRIDE;          // [64]

    const int tid = threadIdx.x;
    const int dq  = blockIdx.x;               // 0..3
    const int z   = blockIdx.y;               // b*H + h
    const int b   = z >> 2;
    const int h   = z & 3;
    const int d0  = dq * DQ;

    if (tid < DQ / 4)
        ((float4*)fw2s)[tid] = ((const float4*)(fw2 + d0))[tid];

    {
        const float4* qb4 = (const float4*)(g_qb + h * HID_ + d0);
        #pragma unroll
        for (int p = 0; p < 2; ++p) {
            int idx = tid + p * 512;
            int u   = idx >> 4;
            int d4  = idx & 15;
            float4 a = ((const float4*)(g_qu + (size_t)(b * U_ + u) * HID_ + d0))[d4];
            float4 qb = qb4[d4];
            a.x += qb.x; a.y += qb.y; a.z += qb.z; a.w += qb.w;
            ((float4*)(qs + u * QSTRIDE))[d4] = a;
        }
    }
    {
        #pragma unroll
        for (int p = 0; p < 4; ++p) {
            int idx = tid + p * 512;
            int t   = idx >> 4;
            int d4  = idx & 15;
            ((float4*)(ks + t * QSTRIDE))[d4] =
                ((const float4*)(g_kh + (size_t)(b * T_ + t) * HID_ + d0))[d4];
        }
    }
    __syncthreads();

    const int tg = tid & 31;       // t = tg + 32*jj
    const int ug = tid >> 5;       // u = 4*ug + i

    ull acc[4][4];
    #pragma unroll
    for (int i = 0; i < 4; ++i)
        #pragma unroll
        for (int jj = 0; jj < 4; ++jj) acc[i][jj] = 0ULL;

    const float* qbase = qs + (ug * 4) * QSTRIDE;
    const float* kbase = ks + tg * QSTRIDE;

    #pragma unroll 4
    for (int d4 = 0; d4 < DQ / 4; ++d4) {
        ulonglong2 wv = *(const ulonglong2*)(fw2s + d4 * 4);
        ulonglong2 qv[4], kv[4];
        #pragma unroll
        for (int i = 0; i < 4; ++i)
            qv[i] = *(const ulonglong2*)(qbase + i * QSTRIDE + d4 * 4);
        #pragma unroll
        for (int jj = 0; jj < 4; ++jj)
            kv[jj] = *(const ulonglong2*)(kbase + jj * 32 * QSTRIDE + d4 * 4);

        #pragma unroll
        for (int i = 0; i < 4; ++i) {
            #pragma unroll
            for (int jj = 0; jj < 4; ++jj) {
                fma2(acc[i][jj], relu2(add2(qv[i].x, kv[jj].x)), wv.x);
                fma2(acc[i][jj], relu2(add2(qv[i].y, kv[jj].y)), wv.y);
            }
        }
    }

    float* part = g_part[dq] + (size_t)z * U_ * T_;
    #pragma unroll
    for (int i = 0; i < 4; ++i) {
        float* row = part + (ug * 4 + i) * T_ + tg;
        #pragma unroll
        for (int jj = 0; jj < 4; ++jj)
            row[jj * 32] = hsum2(acc[i][jj]);
    }
}

// ---------------------------------------------------------------------------
// Combine: out = sum of 4 d-quadrant partials + fb2
// ---------------------------------------------------------------------------
__global__ __launch_bounds__(256) void combine_kernel(
    float* __restrict__ out, const float* __restrict__ fb2)
{
    const float bias = fb2[0];
    int i = blockIdx.x * 256 + threadIdx.x;      // float4 index, 131072 total
    float4 a = ((const float4*)g_part[0])[i];
    float4 b = ((const float4*)g_part[1])[i];
    float4 c = ((const float4*)g_part[2])[i];
    float4 d = ((const float4*)g_part[3])[i];
    float4 r;
    r.x = a.x + b.x + c.x + d.x + bias;
    r.y = a.y + b.y + c.y + d.y + bias;
    r.z = a.z + b.z + c.z + d.z + bias;
    r.w = a.w + b.w + c.w + d.w + bias;
    ((float4*)out)[i] = r;
}

// ---------------------------------------------------------------------------
extern "C" void kernel_launch(void* const* d_in, const int* in_sizes, int n_in,
                              void* d_out, int out_size)
{
    const float* uav_feat = (const float*)d_in[0];
    const float* task_feat = (const float*)d_in[1];
    const float* uw0 = (const float*)d_in[2];
    const float* ub0 = (const float*)d_in[3];
    const float* uw1 = (const float*)d_in[4];
    const float* ub1 = (const float*)d_in[5];
    const float* uw2 = (const float*)d_in[6];
    const float* ub2 = (const float*)d_in[7];
    const float* tw0 = (const float*)d_in[8];
    const float* tb0 = (const float*)d_in[9];
    const float* tw1 = (const float*)d_in[10];
    const float* tb1 = (const float*)d_in[11];
    const float* tw2 = (const float*)d_in[12];
    const float* tb2 = (const float*)d_in[13];
    const float* head_q = (const float*)d_in[14];
    const float* fw1 = (const float*)d_in[15];
    const float* fb1 = (const float*)d_in[16];
    const float* fw2 = (const float*)d_in[17];
    const float* fb2 = (const float*)d_in[18];
    float* out = (float*)d_out;

    cudaFuncSetAttribute(stageE_k,
                         cudaFuncAttributeMaxDynamicSharedMemorySize,
                         SMEM_E_BYTES);

    // Encoders + qb in one launch (385 blocks x 512 threads, 8 rows/block)
    enc_fused_kernel<<<385, 512>>>(uav_feat, task_feat,
                                   uw0, ub0, uw1, ub1, uw2, ub2,
                                   tw0, tb0, tw1, tb1, tw2, tb2,
                                   head_q, fw1, fb1);

    // Stage E over 4 d-quadrants x 64 (b,h)
    dim3 grid(4, B_ * H_);
    stageE_k<<<grid, 512, SMEM_E_BYTES>>>(fw2);

    // Combine partials + bias
    combine_kernel<<<(B_ * H_ * U_ * T_ / 4) / 256, 256>>>(out, fb2);
}

// round 11
// speedup vs baseline: 1.4349x; 1.4349x over previous
#include <cuda_runtime.h>
#include <cstdint>

// Problem dims (fixed)
#define B_  16
#define U_  64
#define T_  128
#define E_  128
#define HID_ 256
#define H_  4
#define ENC_H_ 128
#define IN_DIM_ 32

typedef unsigned long long ull;

// Scratch (device globals: no allocation allowed)
__device__ float g_qu[B_ * U_ * HID_];    // ue @ fw1[:E]          (1024 x 256)
__device__ float g_kh[B_ * T_ * HID_];    // te @ fw1[E:]          (2048 x 256)
__device__ float g_qb[H_ * HID_];         // head_q @ fw1[:E] + fb1 (4 x 256)
__device__ float g_part[4][B_ * H_ * U_ * T_];  // d-quadrant partial sums

// Packed weights: Wp[k2][c] = (W[2k2][c], W[2k2+1][c]) as float2
#define UW0_OFF 0
#define UW1_OFF 4096
#define UW2_OFF 20480
#define TW0_OFF 36864
#define TW1_OFF 40960
#define TW2_OFF 57344
#define FW1_OFF 73728
#define WPACK_TOTAL 139264
__device__ float g_wpack[WPACK_TOTAL];

// ---- packed f32x2 helpers (Blackwell) ----
__device__ __forceinline__ ull add2(ull a, ull b) {
    ull r;
    asm("add.rn.f32x2 %0, %1, %2;" : "=l"(r) : "l"(a), "l"(b));
    return r;
}
__device__ __forceinline__ void fma2(ull& acc, ull a, ull b) {
    asm("fma.rn.f32x2 %0, %1, %2, %0;" : "+l"(acc) : "l"(a), "l"(b));
}
__device__ __forceinline__ ull relu2(ull x) {
    float lo, hi;
    asm("mov.b64 {%0,%1}, %2;" : "=f"(lo), "=f"(hi) : "l"(x));
    lo = fmaxf(lo, 0.f);
    hi = fmaxf(hi, 0.f);
    ull r;
    asm("mov.b64 %0, {%1,%2};" : "=l"(r) : "f"(lo), "f"(hi));
    return r;
}
__device__ __forceinline__ float hsum2(ull x) {
    float lo, hi;
    asm("mov.b64 {%0,%1}, %2;" : "=f"(lo), "=f"(hi) : "l"(x));
    return lo + hi;
}

// ---------------------------------------------------------------------------
// Pack kernel: interleave k-pairs of every weight matrix.
// Segment table (blocks of 256 pairs):
//  [0,8) uw0 | [8,40) uw1 | [40,72) uw2 | [72,80) tw0 | [80,112) tw1
//  [112,144) tw2 | [144,272) fw1
// ---------------------------------------------------------------------------
__global__ __launch_bounds__(256) void pack_kernel(
    const float* __restrict__ uw0, const float* __restrict__ uw1,
    const float* __restrict__ uw2, const float* __restrict__ tw0,
    const float* __restrict__ tw1, const float* __restrict__ tw2,
    const float* __restrict__ fw1)
{
    const int b = blockIdx.x;
    const int t = threadIdx.x;
    const float* src;
    int C, dstoff, pair0;
    if      (b < 8)   { src = uw0; C = 128; dstoff = UW0_OFF; pair0 = b * 256; }
    else if (b < 40)  { src = uw1; C = 128; dstoff = UW1_OFF; pair0 = (b - 8) * 256; }
    else if (b < 72)  { src = uw2; C = 128; dstoff = UW2_OFF; pair0 = (b - 40) * 256; }
    else if (b < 80)  { src = tw0; C = 128; dstoff = TW0_OFF; pair0 = (b - 72) * 256; }
    else if (b < 112) { src = tw1; C = 128; dstoff = TW1_OFF; pair0 = (b - 80) * 256; }
    else if (b < 144) { src = tw2; C = 128; dstoff = TW2_OFF; pair0 = (b - 112) * 256; }
    else              { src = fw1; C = 256; dstoff = FW1_OFF; pair0 = (b - 144) * 256; }

    int p = pair0 + t;
    int k2 = (C == 128) ? (p >> 7) : (p >> 8);
    int c  = (C == 128) ? (p & 127) : (p & 255);
    float lo = src[(2 * k2) * C + c];
    float hi = src[(2 * k2 + 1) * C + c];
    *(float2*)&g_wpack[dstoff + p * 2] = make_float2(lo, hi);
}

// ---------------------------------------------------------------------------
// Packed GEMM tile: 2 rows x 4 cols (cA,cA+1,cB,cB+1) over K.
// act0/act1: smem row pointers (16B aligned). wp: packed weights. C: width.
// ---------------------------------------------------------------------------
__device__ __forceinline__ void gemm_tile(
    ull acc[2][4], const float* act0, const float* act1,
    const float* __restrict__ wp, int C, int K, int cA, int cB)
{
    #pragma unroll 4
    for (int k = 0; k < K; k += 4) {
        int k2 = k >> 1;
        ulonglong2 a0 = *(const ulonglong2*)(act0 + k);
        ulonglong2 a1 = *(const ulonglong2*)(act1 + k);
        ulonglong2 wA0 = __ldg((const ulonglong2*)(wp + (size_t)(k2 * C + cA) * 2));
        ulonglong2 wB0 = __ldg((const ulonglong2*)(wp + (size_t)(k2 * C + cB) * 2));
        ulonglong2 wA1 = __ldg((const ulonglong2*)(wp + (size_t)((k2 + 1) * C + cA) * 2));
        ulonglong2 wB1 = __ldg((const ulonglong2*)(wp + (size_t)((k2 + 1) * C + cB) * 2));
        fma2(acc[0][0], a0.x, wA0.x); fma2(acc[0][1], a0.x, wA0.y);
        fma2(acc[0][2], a0.x, wB0.x); fma2(acc[0][3], a0.x, wB0.y);
        fma2(acc[0][0], a0.y, wA1.x); fma2(acc[0][1], a0.y, wA1.y);
        fma2(acc[0][2], a0.y, wB1.x); fma2(acc[0][3], a0.y, wB1.y);
        fma2(acc[1][0], a1.x, wA0.x); fma2(acc[1][1], a1.x, wA0.y);
        fma2(acc[1][2], a1.x, wB0.x); fma2(acc[1][3], a1.x, wB0.y);
        fma2(acc[1][0], a1.y, wA1.x); fma2(acc[1][1], a1.y, wA1.y);
        fma2(acc[1][2], a1.y, wB1.x); fma2(acc[1][3], a1.y, wB1.y);
    }
}

// ---------------------------------------------------------------------------
// Fused encoder (packed weights): blocks [0,128) = UAV (8 rows), [128,384) =
// task, block 384 = qb.  128 threads = 4 warps.
// lane: rq = lane>>3 -> rows 2rq,2rq+1; cq = lane&7.
// warp w: cols cA = w*16+cq*2 (+1), cB = cA+64 (+1).
// Acts: broadcast LDS.128 (padded strides). W: coalesced 128B LDG.128.
// ---------------------------------------------------------------------------
#define XS_STR 36
#define AS_STR 132

__global__ __launch_bounds__(128, 8) void enc2_kernel(
    const float* __restrict__ uav_feat, const float* __restrict__ task_feat,
    const float* __restrict__ ub0, const float* __restrict__ ub1,
    const float* __restrict__ ub2, const float* __restrict__ tb0,
    const float* __restrict__ tb1, const float* __restrict__ tb2,
    const float* __restrict__ head_q, const float* __restrict__ fw1,
    const float* __restrict__ fb1)
{
    const int bx = blockIdx.x;
    const int tid = threadIdx.x;

    // ---------------- qb block ----------------
    if (bx == 384) {
        for (int d = tid; d < HID_; d += 128) {
            #pragma unroll
            for (int h = 0; h < H_; ++h) {
                float acc = fb1[d];
                #pragma unroll 8
                for (int k = 0; k < E_; ++k)
                    acc += head_q[h * E_ + k] * fw1[k * HID_ + d];
                g_qb[h * HID_ + d] = acc;
            }
        }
        return;
    }

    const int is_task = (bx >= 128);
    const float* x   = is_task ? task_feat : uav_feat;
    const float* wp0 = g_wpack + (is_task ? TW0_OFF : UW0_OFF);
    const float* wp1 = g_wpack + (is_task ? TW1_OFF : UW1_OFF);
    const float* wp2 = g_wpack + (is_task ? TW2_OFF : UW2_OFF);
    const float* wpf = g_wpack + FW1_OFF + (is_task ? E_ * HID_ : 0);
    const float* b0  = is_task ? tb0 : ub0;
    const float* b1  = is_task ? tb1 : ub1;
    const float* b2  = is_task ? tb2 : ub2;
    float* gout      = is_task ? g_kh : g_qu;
    const int row0   = (is_task ? (bx - 128) : bx) * 8;

    __shared__ float xs[8 * XS_STR];
    __shared__ float bufA[8 * AS_STR];
    __shared__ float bufB[8 * AS_STR];

    // load 8x32 input tile
    #pragma unroll
    for (int p = 0; p < 2; ++p) {
        int i = tid + p * 128;
        xs[(i >> 5) * XS_STR + (i & 31)] =
            x[(size_t)(row0 + (i >> 5)) * IN_DIM_ + (i & 31)];
    }
    __syncthreads();

    const int lane = tid & 31;
    const int w    = tid >> 5;        // 0..3
    const int rq   = lane >> 3;       // 0..3
    const int cq   = lane & 7;        // 0..7
    const int r0   = rq * 2;
    const int cA   = w * 16 + cq * 2;
    const int cB   = cA + 64;

    ull acc[2][4];

    // ---- layer 0: 32 -> 128, relu ----
    #pragma unroll
    for (int i = 0; i < 2; ++i)
        #pragma unroll
        for (int jj = 0; jj < 4; ++jj) acc[i][jj] = 0ULL;
    gemm_tile(acc, xs + r0 * XS_STR, xs + (r0 + 1) * XS_STR,
              wp0, ENC_H_, IN_DIM_, cA, cB);
    {
        float2 bA = *(const float2*)(b0 + cA);
        float2 bB = *(const float2*)(b0 + cB);
        #pragma unroll
        for (int r = 0; r < 2; ++r) {
            float* o = bufA + (r0 + r) * AS_STR;
            *(float2*)(o + cA) = make_float2(fmaxf(hsum2(acc[r][0]) + bA.x, 0.f),
                                             fmaxf(hsum2(acc[r][1]) + bA.y, 0.f));
            *(float2*)(o + cB) = make_float2(fmaxf(hsum2(acc[r][2]) + bB.x, 0.f),
                                             fmaxf(hsum2(acc[r][3]) + bB.y, 0.f));
        }
    }
    __syncthreads();

    // ---- layer 1: 128 -> 128, relu ----
    #pragma unroll
    for (int i = 0; i < 2; ++i)
        #pragma unroll
        for (int jj = 0; jj < 4; ++jj) acc[i][jj] = 0ULL;
    gemm_tile(acc, bufA + r0 * AS_STR, bufA + (r0 + 1) * AS_STR,
              wp1, ENC_H_, ENC_H_, cA, cB);
    {
        float2 bA = *(const float2*)(b1 + cA);
        float2 bB = *(const float2*)(b1 + cB);
        #pragma unroll
        for (int r = 0; r < 2; ++r) {
            float* o = bufB + (r0 + r) * AS_STR;
            *(float2*)(o + cA) = make_float2(fmaxf(hsum2(acc[r][0]) + bA.x, 0.f),
                                             fmaxf(hsum2(acc[r][1]) + bA.y, 0.f));
            *(float2*)(o + cB) = make_float2(fmaxf(hsum2(acc[r][2]) + bB.x, 0.f),
                                             fmaxf(hsum2(acc[r][3]) + bB.y, 0.f));
        }
    }
    __syncthreads();

    // ---- layer 2: 128 -> 128 (no relu), writes bufA (dead after L1) ----
    #pragma unroll
    for (int i = 0; i < 2; ++i)
        #pragma unroll
        for (int jj = 0; jj < 4; ++jj) acc[i][jj] = 0ULL;
    gemm_tile(acc, bufB + r0 * AS_STR, bufB + (r0 + 1) * AS_STR,
              wp2, ENC_H_, ENC_H_, cA, cB);
    {
        float2 bA = *(const float2*)(b2 + cA);
        float2 bB = *(const float2*)(b2 + cB);
        #pragma unroll
        for (int r = 0; r < 2; ++r) {
            float* o = bufA + (r0 + r) * AS_STR;
            *(float2*)(o + cA) = make_float2(hsum2(acc[r][0]) + bA.x,
                                             hsum2(acc[r][1]) + bA.y);
            *(float2*)(o + cB) = make_float2(hsum2(acc[r][2]) + bB.x,
                                             hsum2(acc[r][3]) + bB.y);
        }
    }
    __syncthreads();

    // ---- projection through fw1 slice: 128 -> 256, two col passes ----
    #pragma unroll
    for (int p = 0; p < 2; ++p) {
        #pragma unroll
        for (int i = 0; i < 2; ++i)
            #pragma unroll
            for (int jj = 0; jj < 4; ++jj) acc[i][jj] = 0ULL;
        gemm_tile(acc, bufA + r0 * AS_STR, bufA + (r0 + 1) * AS_STR,
                  wpf, HID_, E_, cA + 128 * p, cB + 128 * p);
        #pragma unroll
        for (int r = 0; r < 2; ++r) {
            float* o = gout + (size_t)(row0 + r0 + r) * HID_ + 128 * p;
            *(float2*)(o + cA) = make_float2(hsum2(acc[r][0]), hsum2(acc[r][1]));
            *(float2*)(o + cB) = make_float2(hsum2(acc[r][2]), hsum2(acc[r][3]));
        }
    }
}

// ---------------------------------------------------------------------------
// Stage E (d-split): partial[dq][z][u][t] =
//   sum_{d in quad} relu(qu[b,u,d]+qb[h,d]+kh[b,t,d]) * fw2[d]
// Block: (dq, z). Tile 64u x 128t x 64d, 512 threads, thread tile 4u x 4t.
// ---------------------------------------------------------------------------
#define DQ 64
#define QSTRIDE 68
#define SMEM_E_FLOATS (64 * QSTRIDE + 128 * QSTRIDE + DQ)
#define SMEM_E_BYTES  (SMEM_E_FLOATS * 4)

__global__ __launch_bounds__(512, 2) void stageE_k(
    const float* __restrict__ fw2)
{
    extern __shared__ float smem[];
    float* qs   = smem;                        // [64][68]
    float* ks   = smem + 64 * QSTRIDE;         // [128][68]
    float* fw2s = ks + 128 * QSTRIDE;          // [64]

    const int tid = threadIdx.x;
    const int dq  = blockIdx.x;               // 0..3
    const int z   = blockIdx.y;               // b*H + h
    const int b   = z >> 2;
    const int h   = z & 3;
    const int d0  = dq * DQ;

    if (tid < DQ / 4)
        ((float4*)fw2s)[tid] = ((const float4*)(fw2 + d0))[tid];

    {
        const float4* qb4 = (const float4*)(g_qb + h * HID_ + d0);
        #pragma unroll
        for (int p = 0; p < 2; ++p) {
            int idx = tid + p * 512;
            int u   = idx >> 4;
            int d4  = idx & 15;
            float4 a = ((const float4*)(g_qu + (size_t)(b * U_ + u) * HID_ + d0))[d4];
            float4 qb = qb4[d4];
            a.x += qb.x; a.y += qb.y; a.z += qb.z; a.w += qb.w;
            ((float4*)(qs + u * QSTRIDE))[d4] = a;
        }
    }
    {
        #pragma unroll
        for (int p = 0; p < 4; ++p) {
            int idx = tid + p * 512;
            int t   = idx >> 4;
            int d4  = idx & 15;
            ((float4*)(ks + t * QSTRIDE))[d4] =
                ((const float4*)(g_kh + (size_t)(b * T_ + t) * HID_ + d0))[d4];
        }
    }
    __syncthreads();

    const int tg = tid & 31;       // t = tg + 32*jj
    const int ug = tid >> 5;       // u = 4*ug + i

    ull acc[4][4];
    #pragma unroll
    for (int i = 0; i < 4; ++i)
        #pragma unroll
        for (int jj = 0; jj < 4; ++jj) acc[i][jj] = 0ULL;

    const float* qbase = qs + (ug * 4) * QSTRIDE;
    const float* kbase = ks + tg * QSTRIDE;

    #pragma unroll 4
    for (int d4 = 0; d4 < DQ / 4; ++d4) {
        ulonglong2 wv = *(const ulonglong2*)(fw2s + d4 * 4);
        ulonglong2 qv[4], kv[4];
        #pragma unroll
        for (int i = 0; i < 4; ++i)
            qv[i] = *(const ulonglong2*)(qbase + i * QSTRIDE + d4 * 4);
        #pragma unroll
        for (int jj = 0; jj < 4; ++jj)
            kv[jj] = *(const ulonglong2*)(kbase + jj * 32 * QSTRIDE + d4 * 4);

        #pragma unroll
        for (int i = 0; i < 4; ++i) {
            #pragma unroll
            for (int jj = 0; jj < 4; ++jj) {
                fma2(acc[i][jj], relu2(add2(qv[i].x, kv[jj].x)), wv.x);
                fma2(acc[i][jj], relu2(add2(qv[i].y, kv[jj].y)), wv.y);
            }
        }
    }

    float* part = g_part[dq] + (size_t)z * U_ * T_;
    #pragma unroll
    for (int i = 0; i < 4; ++i) {
        float* row = part + (ug * 4 + i) * T_ + tg;
        #pragma unroll
        for (int jj = 0; jj < 4; ++jj)
            row[jj * 32] = hsum2(acc[i][jj]);
    }
}

// ---------------------------------------------------------------------------
// Combine: out = sum of 4 d-quadrant partials + fb2
// ---------------------------------------------------------------------------
__global__ __launch_bounds__(256) void combine_kernel(
    float* __restrict__ out, const float* __restrict__ fb2)
{
    const float bias = fb2[0];
    int i = blockIdx.x * 256 + threadIdx.x;      // float4 index, 131072 total
    float4 a = ((const float4*)g_part[0])[i];
    float4 b = ((const float4*)g_part[1])[i];
    float4 c = ((const float4*)g_part[2])[i];
    float4 d = ((const float4*)g_part[3])[i];
    float4 r;
    r.x = a.x + b.x + c.x + d.x + bias;
    r.y = a.y + b.y + c.y + d.y + bias;
    r.z = a.z + b.z + c.z + d.z + bias;
    r.w = a.w + b.w + c.w + d.w + bias;
    ((float4*)out)[i] = r;
}

// ---------------------------------------------------------------------------
extern "C" void kernel_launch(void* const* d_in, const int* in_sizes, int n_in,
                              void* d_out, int out_size)
{
    const float* uav_feat = (const float*)d_in[0];
    const float* task_feat = (const float*)d_in[1];
    const float* uw0 = (const float*)d_in[2];
    const float* ub0 = (const float*)d_in[3];
    const float* uw1 = (const float*)d_in[4];
    const float* ub1 = (const float*)d_in[5];
    const float* uw2 = (const float*)d_in[6];
    const float* ub2 = (const float*)d_in[7];
    const float* tw0 = (const float*)d_in[8];
    const float* tb0 = (const float*)d_in[9];
    const float* tw1 = (const float*)d_in[10];
    const float* tb1 = (const float*)d_in[11];
    const float* tw2 = (const float*)d_in[12];
    const float* tb2 = (const float*)d_in[13];
    const float* head_q = (const float*)d_in[14];
    const float* fw1 = (const float*)d_in[15];
    const float* fb1 = (const float*)d_in[16];
    const float* fw2 = (const float*)d_in[17];
    const float* fb2 = (const float*)d_in[18];
    float* out = (float*)d_out;

    cudaFuncSetAttribute(stageE_k,
                         cudaFuncAttributeMaxDynamicSharedMemorySize,
                         SMEM_E_BYTES);

    // 1) pack weights into k-pair-interleaved layout
    pack_kernel<<<272, 256>>>(uw0, uw1, uw2, tw0, tw1, tw2, fw1);

    // 2) encoders + qb (385 blocks x 128 threads, 8 rows/block)
    enc2_kernel<<<385, 128>>>(uav_feat, task_feat,
                              ub0, ub1, ub2, tb0, tb1, tb2,
                              head_q, fw1, fb1);

    // 3) Stage E over 4 d-quadrants x 64 (b,h)
    dim3 grid(4, B_ * H_);
    stageE_k<<<grid, 512, SMEM_E_BYTES>>>(fw2);

    // 4) combine partials + bias
    combine_kernel<<<(B_ * H_ * U_ * T_ / 4) / 256, 256>>>(out, fb2);
}